// round 11
// baseline (speedup 1.0000x reference)
#include <cuda_runtime.h>
#include <cuda_fp16.h>
#include <cuda_fp8.h>

// Sinkhorn on s[B=32, N=1024, M=1024], MAX_ITER=15, EPS=1e-4.
//
// Single persistent kernel (R10 structure). Factored form
// s_t = r_i * s0_ij * c_j. 512-thread blocks; block k of batch b owns rows
// [128k,128k+128); halves own 64 rows each. 8 blocks/batch sync via a
// batch-local monotonic barrier; column partials double-buffered in g_part.
//
// Precision schedule: iterations 1..10 sweep an e4m3 fp8 copy (32 MB);
// iterations 11..14 and the finalize sweep the fp16 copy (64 MB). Errors
// injected by fp8 act as row/col rescalings of the input, which Sinkhorn
// renormalizes away over the remaining fp16 iterations.

#define BB 32
#define NN 1024
#define MM 1024
#define EPSF 1e-4f
#define KB_ 8             // blocks per batch
#define RPB (NN / KB_)    // 128 rows per block
#define HROWS 64          // rows per half
#define TPB 512
#define FP8_HALVES 5      // halves 0..4 (it 1..10) use fp8 sweeps

__device__ __half2 g_h[(size_t)BB * NN * MM / 2];   // 64 MB fp16 copy
__device__ unsigned g_q4[(size_t)BB * NN * MM / 4]; // 32 MB fp8 copy
__device__ float g_part[2][BB * KB_ * MM];          // double-buffered partials
__device__ int g_cnt2[BB];                          // zero-init
__device__ int g_flag[BB];                          // monotonic, persists

// ---------------------------------------------------------------------------
__device__ __forceinline__ void batch_barrier(int b, int& nextv) {
    __threadfence();
    __syncthreads();
    nextv += 1;
    if (threadIdx.x == 0) {
        int old = atomicAdd(&g_cnt2[b], 1);
        if (old == KB_ - 1) {
            atomicExch(&g_cnt2[b], 0);
            __threadfence();
            *(volatile int*)&g_flag[b] = nextv;
        } else {
            while (*(volatile int*)&g_flag[b] - nextv < 0) __nanosleep(32);
        }
        __threadfence();
    }
    __syncthreads();
}

// decode 4 fp8 (e4m3) packed in a uint -> two float2
__device__ __forceinline__ void fp8x4_to_f32(unsigned v, float2& f0,
                                             float2& f1) {
    __half2_raw hlo = __nv_cvt_fp8x2_to_halfraw2(
        (__nv_fp8x2_storage_t)(v & 0xffffu), __NV_E4M3);
    __half2_raw hhi = __nv_cvt_fp8x2_to_halfraw2(
        (__nv_fp8x2_storage_t)(v >> 16), __NV_E4M3);
    f0 = __half22float2(*(__half2*)&hlo);
    f1 = __half22float2(*(__half2*)&hhi);
}

// ---------------------------------------------------------------------------
__global__ void __launch_bounds__(TPB, 2)
sinkhorn_kernel(const float* __restrict__ s, float* __restrict__ out) {
    const int bx = blockIdx.x;
    const int b = bx >> 3;         // batch
    const int k = bx & (KB_ - 1);  // block within batch
    const int tid = threadIdx.x;
    const int half = tid >> 8;     // 0 or 1
    const int ct = tid & 255;      // column group: owns cols [4ct, 4ct+4)

    __shared__ float sc[MM];       // column scaling c (full vector)
    __shared__ float sr[RPB];      // row scaling r (own 128 rows)
    __shared__ float scomb[MM];    // half-combine buffer (4 KB)

    int nextv = *(volatile int*)&g_flag[b];  // barrier base

    const size_t hrow0 = (size_t)(b * NN + k * RPB + half * HROWS);

    // ---------------- it = 0: fp32 -> {fp16, fp8} conversion + col partials
    {
        const float4* sp = (const float4*)(s + hrow0 * MM) + ct;
        __half2* hp = g_h + hrow0 * (MM / 2) + ct * 2;
        unsigned* qp = g_q4 + hrow0 * (MM / 4) + ct;
        float4 acc = make_float4(0.f, 0.f, 0.f, 0.f);
#pragma unroll 4
        for (int i = 0; i < HROWS; i++) {
            float4 v = sp[(size_t)i * (MM / 4)];
            __half2 h0 = __floats2half2_rn(v.x, v.y);
            __half2 h1 = __floats2half2_rn(v.z, v.w);
            uint2 o;
            o.x = *(unsigned*)&h0;
            o.y = *(unsigned*)&h1;
            *(uint2*)(hp + (size_t)i * (MM / 2)) = o;
            unsigned q0 = __nv_cvt_float2_to_fp8x2(
                make_float2(v.x, v.y), __NV_SATFINITE, __NV_E4M3);
            unsigned q1 = __nv_cvt_float2_to_fp8x2(
                make_float2(v.z, v.w), __NV_SATFINITE, __NV_E4M3);
            qp[(size_t)i * (MM / 4)] = q0 | (q1 << 16);
            acc.x += v.x; acc.y += v.y; acc.z += v.z; acc.w += v.w;
        }
        if (half) *(float4*)&scomb[ct * 4] = acc;
        __syncthreads();
        if (!half) {
            float4 o2 = *(float4*)&scomb[ct * 4];
            acc.x += o2.x; acc.y += o2.y; acc.z += o2.z; acc.w += o2.w;
            *(float4*)&g_part[0][((size_t)(b * KB_ + k)) * MM + ct * 4] = acc;
        }
    }
    batch_barrier(b, nextv);

    // c init (c_old = 1): split reduce across halves.
    {
        const int j = ct * 4;
        float4 p = make_float4(0.f, 0.f, 0.f, 0.f);
#pragma unroll
        for (int q = 0; q < KB_ / 2; q++) {
            const int qq = half * (KB_ / 2) + q;
            const float4 v = __ldcg(
                (const float4*)&g_part[0][((size_t)(b * KB_ + qq)) * MM + j]);
            p.x += v.x; p.y += v.y; p.z += v.z; p.w += v.w;
        }
        if (half) *(float4*)&scomb[j] = p;
        __syncthreads();
        if (!half) {
            float4 o2 = *(float4*)&scomb[j];
            p.x += o2.x; p.y += o2.y; p.z += o2.z; p.w += o2.w;
            sc[j + 0] = 1.0f / (p.x + EPSF);
            sc[j + 1] = 1.0f / (p.y + EPSF);
            sc[j + 2] = 1.0f / (p.z + EPSF);
            sc[j + 3] = 1.0f / (p.w + EPSF);
        }
    }
    __syncthreads();

    // ---------------- 7 x (row step it=2h+1, col step it=2h+2)
    const int warp = tid >> 5;     // 0..15
    const int lane = tid & 31;
    const size_t brow0 = (size_t)(b * NN + k * RPB);

    for (int hh = 0; hh < 7; hh++) {
        const bool use8 = (hh < FP8_HALVES);

        // ---- row step: warp w handles rows [8w, 8w+8) of the 128-row slice
        if (use8) {
#pragma unroll
            for (int rr = 0; rr < RPB / 16; rr++) {
                const int i = warp * (RPB / 16) + rr;
                const unsigned* qp = g_q4 + (brow0 + i) * (MM / 4);
                float acc = 0.f;
#pragma unroll
                for (int kk = 0; kk < 8; kk++) {
                    unsigned v = qp[kk * 32 + lane];
                    float2 f0, f1;
                    fp8x4_to_f32(v, f0, f1);
                    int jj = (kk * 32 + lane) * 4;
                    acc = fmaf(f0.x, sc[jj + 0], acc);
                    acc = fmaf(f0.y, sc[jj + 1], acc);
                    acc = fmaf(f1.x, sc[jj + 2], acc);
                    acc = fmaf(f1.y, sc[jj + 3], acc);
                }
#pragma unroll
                for (int o = 16; o > 0; o >>= 1)
                    acc += __shfl_xor_sync(0xffffffffu, acc, o);
                if (lane == 0) {
                    float r = (hh == 0) ? 1.0f : sr[i];
                    sr[i] = r / fmaf(r, acc, EPSF);
                }
            }
        } else {
#pragma unroll
            for (int rr = 0; rr < RPB / 16; rr++) {
                const int i = warp * (RPB / 16) + rr;
                const uint4* hp = (const uint4*)(g_h + (brow0 + i) * (MM / 2));
                float acc = 0.f;
#pragma unroll
                for (int kk = 0; kk < 4; kk++) {
                    int v4 = kk * 32 + lane;
                    uint4 v = hp[v4];
                    int jj = v4 * 8;
                    float2 f0 = __half22float2(*(__half2*)&v.x);
                    float2 f1 = __half22float2(*(__half2*)&v.y);
                    float2 f2 = __half22float2(*(__half2*)&v.z);
                    float2 f3 = __half22float2(*(__half2*)&v.w);
                    acc = fmaf(f0.x, sc[jj + 0], acc);
                    acc = fmaf(f0.y, sc[jj + 1], acc);
                    acc = fmaf(f1.x, sc[jj + 2], acc);
                    acc = fmaf(f1.y, sc[jj + 3], acc);
                    acc = fmaf(f2.x, sc[jj + 4], acc);
                    acc = fmaf(f2.y, sc[jj + 5], acc);
                    acc = fmaf(f3.x, sc[jj + 6], acc);
                    acc = fmaf(f3.y, sc[jj + 7], acc);
                }
#pragma unroll
                for (int o = 16; o > 0; o >>= 1)
                    acc += __shfl_xor_sync(0xffffffffu, acc, o);
                if (lane == 0) {
                    float r = (hh == 0) ? 1.0f : sr[i];
                    sr[i] = r / fmaf(r, acc, EPSF);
                }
            }
        }
        __syncthreads();

        // ---- col step partials: P_j += r_i * h_ij over this half's 64 rows
        const int buf = (hh + 1) & 1;
        {
            const float* srh = sr + half * HROWS;
            float4 acc = make_float4(0.f, 0.f, 0.f, 0.f);
            if (use8) {
                const unsigned* qp = g_q4 + hrow0 * (MM / 4) + ct;
#pragma unroll 8
                for (int i = 0; i < HROWS; i++) {
                    unsigned v = qp[(size_t)i * (MM / 4)];
                    float rw = srh[i];
                    float2 f0, f1;
                    fp8x4_to_f32(v, f0, f1);
                    acc.x = fmaf(rw, f0.x, acc.x);
                    acc.y = fmaf(rw, f0.y, acc.y);
                    acc.z = fmaf(rw, f1.x, acc.z);
                    acc.w = fmaf(rw, f1.y, acc.w);
                }
            } else {
                const uint2* hp = (const uint2*)(g_h + hrow0 * (MM / 2)) + ct;
#pragma unroll 8
                for (int i = 0; i < HROWS; i++) {
                    uint2 v = hp[(size_t)i * (MM / 4)];
                    float rw = srh[i];
                    float2 f0 = __half22float2(*(__half2*)&v.x);
                    float2 f1 = __half22float2(*(__half2*)&v.y);
                    acc.x = fmaf(rw, f0.x, acc.x);
                    acc.y = fmaf(rw, f0.y, acc.y);
                    acc.z = fmaf(rw, f1.x, acc.z);
                    acc.w = fmaf(rw, f1.y, acc.w);
                }
            }
            if (half) *(float4*)&scomb[ct * 4] = acc;
            __syncthreads();
            if (!half) {
                float4 o2 = *(float4*)&scomb[ct * 4];
                acc.x += o2.x; acc.y += o2.y; acc.z += o2.z; acc.w += o2.w;
                *(float4*)&g_part[buf][((size_t)(b * KB_ + k)) * MM + ct * 4] =
                    acc;
            }
        }
        batch_barrier(b, nextv);

        // ---- reduce partials -> c update (per block; split across halves)
        {
            const int j = ct * 4;
            float4 p = make_float4(0.f, 0.f, 0.f, 0.f);
#pragma unroll
            for (int q = 0; q < KB_ / 2; q++) {
                const int qq = half * (KB_ / 2) + q;
                const float4 v = __ldcg((const float4*)
                    &g_part[buf][((size_t)(b * KB_ + qq)) * MM + j]);
                p.x += v.x; p.y += v.y; p.z += v.z; p.w += v.w;
            }
            if (half) *(float4*)&scomb[j] = p;
            __syncthreads();
            if (!half) {
                float4 o2 = *(float4*)&scomb[j];
                p.x += o2.x; p.y += o2.y; p.z += o2.z; p.w += o2.w;
                float4 c = *(float4*)&sc[j];
                c.x = c.x / fmaf(c.x, p.x, EPSF);
                c.y = c.y / fmaf(c.y, p.y, EPSF);
                c.z = c.z / fmaf(c.z, p.z, EPSF);
                c.w = c.w / fmaf(c.w, p.w, EPSF);
                *(float4*)&sc[j] = c;
            }
        }
        __syncthreads();
    }

    // ---------------- finalize: out = r_i * h_ij * c_j (fp16 copy, L2-hot)
    {
        const int j = ct * 4;
        const float4 c4 = *(float4*)&sc[j];
        const float* srh = sr + half * HROWS;
        const uint2* hp = (const uint2*)(g_h + hrow0 * (MM / 2)) + ct;
        float4* op = (float4*)(out + hrow0 * MM) + ct;
#pragma unroll 4
        for (int i = 0; i < HROWS; i++) {
            const float r = srh[i];
            uint2 v = hp[(size_t)i * (MM / 4)];
            float2 f0 = __half22float2(*(__half2*)&v.x);
            float2 f1 = __half22float2(*(__half2*)&v.y);
            float4 o;
            o.x = r * f0.x * c4.x;
            o.y = r * f0.y * c4.y;
            o.z = r * f1.x * c4.z;
            o.w = r * f1.y * c4.w;
            op[(size_t)i * (MM / 4)] = o;
        }
    }
}

// ---------------------------------------------------------------------------
extern "C" void kernel_launch(void* const* d_in, const int* in_sizes, int n_in,
                              void* d_out, int out_size) {
    const float* s = (const float*)d_in[0];
    float* out = (float*)d_out;
    sinkhorn_kernel<<<BB * KB_, TPB>>>(s, out);
}